// round 2
// baseline (speedup 1.0000x reference)
#include <cuda_runtime.h>

// TaylorExp: out row (273) = [1, x*0.5 (16), outer(sx,sx) (256)]
// sx = x * sqrt(1/(sqrt(2)*sqrt(16)))
//
// Round-2: compute rows into smem, flush with aligned STG.128.
// 8 rows/block * 273 floats = 2184 floats = 8736 B (16B-aligned per block).

#define QUAD_SQRT_SCALE 0.42044820762685725f
#define T1_SCALE        0.5f
#define ROWS_PER_BLOCK  8
#define ROW_LEN         273
#define BLOCK_FLOATS    (ROWS_PER_BLOCK * ROW_LEN)   // 2184
#define BLOCK_FLOAT4S   (BLOCK_FLOATS / 4)           // 546

__global__ void __launch_bounds__(256) taylor_exp_kernel(
    const float* __restrict__ x,
    float* __restrict__ out,
    int rows)
{
    __shared__ __align__(16) float s[BLOCK_FLOATS];

    const int warp = threadIdx.x >> 5;
    const int lane = threadIdx.x & 31;
    const int row  = blockIdx.x * ROWS_PER_BLOCK + warp;

    if (row < rows) {
        float* __restrict__ srow = s + warp * ROW_LEN;
        float xv = (lane < 16) ? x[(size_t)row * 16 + lane] : 0.0f;

        if (lane < 16)  srow[1 + lane] = xv * T1_SCALE;
        if (lane == 16) srow[0] = 1.0f;

        float sx = xv * QUAD_SQRT_SCALE;
        #pragma unroll
        for (int k = 0; k < 8; k++) {
            int q = lane + 32 * k;                       // 0..255
            float vr = __shfl_sync(0xffffffffu, sx, q >> 4);
            float vc = __shfl_sync(0xffffffffu, sx, q & 15);
            srow[17 + q] = vr * vc;
        }
    }
    __syncthreads();

    const size_t base = (size_t)blockIdx.x * BLOCK_FLOATS;
    const int valid_rows = min(ROWS_PER_BLOCK, rows - blockIdx.x * ROWS_PER_BLOCK);

    if (valid_rows == ROWS_PER_BLOCK) {
        // aligned 128-bit flush: 546 float4s with 256 threads
        const float4* __restrict__ s4 = (const float4*)s;
        float4* __restrict__ o4 = (float4*)(out + base);
        #pragma unroll
        for (int i = threadIdx.x; i < BLOCK_FLOAT4S; i += 256)
            o4[i] = s4[i];
    } else if (valid_rows > 0) {
        // tail block: scalar bounds-checked flush
        const int nfloats = valid_rows * ROW_LEN;
        for (int i = threadIdx.x; i < nfloats; i += 256)
            out[base + i] = s[i];
    }
}

extern "C" void kernel_launch(void* const* d_in, const int* in_sizes, int n_in,
                              void* d_out, int out_size)
{
    const float* x = (const float*)d_in[0];
    float* out = (float*)d_out;

    int rows = in_sizes[0] / 16;
    int blocks = (rows + ROWS_PER_BLOCK - 1) / ROWS_PER_BLOCK;

    taylor_exp_kernel<<<blocks, 256>>>(x, out, rows);
}

// round 3
// speedup vs baseline: 1.1713x; 1.1713x over previous
#include <cuda_runtime.h>
#include <cstdint>

// TaylorExp: out row (273) = [1, x*0.5 (16), outer(sx,sx) (256)]
// sx = x * sqrt(1/(sqrt(2)*sqrt(16)))
//
// Round-3: compute rows into smem (cheap STS, conflict-free), flush the whole
// 8-row block with one TMA bulk store (cp.async.bulk) so the per-thread L1tex
// store pipeline is bypassed entirely.

#define QUAD_SQRT_SCALE 0.42044820762685725f
#define T1_SCALE        0.5f
#define ROWS_PER_BLOCK  8
#define ROW_LEN         273
#define BLOCK_FLOATS    (ROWS_PER_BLOCK * ROW_LEN)   // 2184
#define BLOCK_BYTES     (BLOCK_FLOATS * 4)           // 8736, multiple of 16

__global__ void __launch_bounds__(256) taylor_exp_kernel(
    const float* __restrict__ x,
    float* __restrict__ out,
    int rows)
{
    __shared__ __align__(16) float s[BLOCK_FLOATS];

    const int warp = threadIdx.x >> 5;
    const int lane = threadIdx.x & 31;
    const int row  = blockIdx.x * ROWS_PER_BLOCK + warp;

    if (row < rows) {
        float* __restrict__ srow = s + warp * ROW_LEN;
        float xv = (lane < 16) ? x[(size_t)row * 16 + lane] : 0.0f;

        if (lane < 16)  srow[1 + lane] = xv * T1_SCALE;
        if (lane == 16) srow[0] = 1.0f;

        float sx = xv * QUAD_SQRT_SCALE;
        #pragma unroll
        for (int k = 0; k < 8; k++) {
            int q = lane + 32 * k;                       // 0..255
            float vr = __shfl_sync(0xffffffffu, sx, q >> 4);
            float vc = __shfl_sync(0xffffffffu, sx, q & 15);
            srow[17 + q] = vr * vc;
        }
    }
    __syncthreads();

    const size_t base = (size_t)blockIdx.x * BLOCK_FLOATS;
    const int valid_rows = min(ROWS_PER_BLOCK, rows - blockIdx.x * ROWS_PER_BLOCK);

    if (valid_rows == ROWS_PER_BLOCK) {
        // One bulk async smem -> gmem copy for the whole block's output.
        if (threadIdx.x == 0) {
            uint32_t saddr = (uint32_t)__cvta_generic_to_shared(s);
            float* gdst = out + base;
            asm volatile("fence.proxy.async.shared::cta;" ::: "memory");
            asm volatile(
                "cp.async.bulk.global.shared::cta.bulk_group [%0], [%1], %2;"
                :: "l"(gdst), "r"(saddr), "r"((uint32_t)BLOCK_BYTES)
                : "memory");
            asm volatile("cp.async.bulk.commit_group;" ::: "memory");
            asm volatile("cp.async.bulk.wait_group 0;" ::: "memory");
        }
    } else if (valid_rows > 0) {
        // tail block: scalar bounds-checked flush (not hit for bench shape)
        const int nfloats = valid_rows * ROW_LEN;
        for (int i = threadIdx.x; i < nfloats; i += 256)
            out[base + i] = s[i];
    }
}

extern "C" void kernel_launch(void* const* d_in, const int* in_sizes, int n_in,
                              void* d_out, int out_size)
{
    const float* x = (const float*)d_in[0];
    float* out = (float*)d_out;

    int rows = in_sizes[0] / 16;
    int blocks = (rows + ROWS_PER_BLOCK - 1) / ROWS_PER_BLOCK;

    taylor_exp_kernel<<<blocks, 256>>>(x, out, rows);
}

// round 4
// speedup vs baseline: 1.4061x; 1.2004x over previous
#include <cuda_runtime.h>
#include <cstdint>

// TaylorExp: out row (273) = [1, x*0.5 (16), outer(sx,sx) (256)]
// sx = x * sqrt(1/(sqrt(2)*sqrt(16)))
//
// Round-4: R3 structure (smem compute + one TMA bulk store per block) plus an
// L2::evict_first cache policy on the bulk store so the 286MB write stream
// drains to DRAM in sequential order instead of LRU-scattered evictions.

#define QUAD_SQRT_SCALE 0.42044820762685725f
#define T1_SCALE        0.5f
#define ROWS_PER_BLOCK  8
#define ROW_LEN         273
#define BLOCK_FLOATS    (ROWS_PER_BLOCK * ROW_LEN)   // 2184
#define BLOCK_BYTES     (BLOCK_FLOATS * 4)           // 8736 = 273 * 32  (sector-aligned)

__global__ void __launch_bounds__(256) taylor_exp_kernel(
    const float* __restrict__ x,
    float* __restrict__ out,
    int rows)
{
    __shared__ __align__(16) float s[BLOCK_FLOATS];

    const int warp = threadIdx.x >> 5;
    const int lane = threadIdx.x & 31;
    const int row  = blockIdx.x * ROWS_PER_BLOCK + warp;

    if (row < rows) {
        float* __restrict__ srow = s + warp * ROW_LEN;
        float xv = (lane < 16) ? x[(size_t)row * 16 + lane] : 0.0f;

        if (lane < 16)  srow[1 + lane] = xv * T1_SCALE;
        if (lane == 16) srow[0] = 1.0f;

        float sx = xv * QUAD_SQRT_SCALE;
        #pragma unroll
        for (int k = 0; k < 8; k++) {
            int q = lane + 32 * k;                       // 0..255
            float vr = __shfl_sync(0xffffffffu, sx, q >> 4);
            float vc = __shfl_sync(0xffffffffu, sx, q & 15);
            srow[17 + q] = vr * vc;
        }
    }
    __syncthreads();

    const size_t base = (size_t)blockIdx.x * BLOCK_FLOATS;
    const int valid_rows = min(ROWS_PER_BLOCK, rows - blockIdx.x * ROWS_PER_BLOCK);

    if (valid_rows == ROWS_PER_BLOCK) {
        // One bulk async smem -> gmem copy, with evict_first L2 policy so the
        // dirty write stream drains sequentially instead of via LRU scatter.
        if (threadIdx.x == 0) {
            uint32_t saddr = (uint32_t)__cvta_generic_to_shared(s);
            float* gdst = out + base;
            asm volatile("fence.proxy.async.shared::cta;" ::: "memory");
            asm volatile(
                "{\n\t"
                ".reg .b64 pol;\n\t"
                "createpolicy.fractional.L2::evict_first.b64 pol, 1.0;\n\t"
                "cp.async.bulk.global.shared::cta.bulk_group.L2::cache_hint"
                " [%0], [%1], %2, pol;\n\t"
                "}"
                :: "l"(gdst), "r"(saddr), "r"((uint32_t)BLOCK_BYTES)
                : "memory");
            asm volatile("cp.async.bulk.commit_group;" ::: "memory");
            asm volatile("cp.async.bulk.wait_group 0;" ::: "memory");
        }
    } else if (valid_rows > 0) {
        // tail block: scalar bounds-checked flush (not hit for bench shape)
        const int nfloats = valid_rows * ROW_LEN;
        for (int i = threadIdx.x; i < nfloats; i += 256)
            out[base + i] = s[i];
    }
}

extern "C" void kernel_launch(void* const* d_in, const int* in_sizes, int n_in,
                              void* d_out, int out_size)
{
    const float* x = (const float*)d_in[0];
    float* out = (float*)d_out;

    int rows = in_sizes[0] / 16;
    int blocks = (rows + ROWS_PER_BLOCK - 1) / ROWS_PER_BLOCK;

    taylor_exp_kernel<<<blocks, 256>>>(x, out, rows);
}